// round 13
// baseline (speedup 1.0000x reference)
#include <cuda_runtime.h>
#include <cstdint>

#define NC      6
#define NWARPS  8
#define TPB     256
#define NBLOCKS 1184   // 148 SMs * 8
#define NVALS   13     // ht[6], hp[6], dsum
#define PF_DIST 4      // grid-strides ahead for L2 prefetch (~58MB window)

// Per-block partials, [val][block]; fully overwritten each launch.
__device__ unsigned int g_part[NVALS][NBLOCKS];
__device__ unsigned int g_ticket;   // last-block-done counter; reset by last block

__device__ __forceinline__ void l2_prefetch(const void* p) {
    asm volatile("prefetch.global.L2 [%0];" :: "l"(p));
}

__global__ void __launch_bounds__(TPB) kappa_fused_kernel(
    const float* __restrict__ yp,
    const int* __restrict__ yt,     // y_true is int32 (JAX x64-demotion)
    int n,
    float* __restrict__ out)
{
    const int tid  = threadIdx.x;
    const int warp = tid >> 5;
    const int lane = tid & 31;

    // Register accumulators: packed 6x10-bit histograms + squared-diff sum.
    unsigned long long ht_pack = 0ull;
    unsigned long long hp_pack = 0ull;
    unsigned int dsum = 0u;

    const int ngroups = n >> 1;                   // groups of 2 rows
    const float4* yp4 = (const float4*)yp;        // 3 float4 per group (12 floats)
    const int2*   yt2 = (const int2*)yt;          // 1 int2 per group (2 labels)
    const int stride = gridDim.x * blockDim.x;

    for (int g = blockIdx.x * blockDim.x + tid; g < ngroups; g += stride) {
        // Fire-and-forget L2 prefetch PF_DIST strides ahead: costs no register,
        // no scoreboard slot. 48B/thread < 128B line => collective coverage of
        // every line; duplicate intra-warp addresses coalesce in the LSU.
        {
            const long long gp = (long long)g + (long long)PF_DIST * stride;
            if (gp < ngroups) {
                const uintptr_t a = (uintptr_t)&yp4[(size_t)gp * 3];
                l2_prefetch((const void*)(a & ~(uintptr_t)127));
                const uintptr_t b = (uintptr_t)&yt2[gp];
                l2_prefetch((const void*)(b & ~(uintptr_t)127));
            }
        }

        float4 f0 = __ldcg(&yp4[(size_t)g * 3 + 0]);
        float4 f1 = __ldcg(&yp4[(size_t)g * 3 + 1]);
        float4 f2 = __ldcg(&yp4[(size_t)g * 3 + 2]);
        int2   t2 = __ldcg(&yt2[g]);

        float v[12];
        v[0]=f0.x; v[1]=f0.y; v[2]=f0.z;  v[3]=f0.w;
        v[4]=f1.x; v[5]=f1.y; v[6]=f1.z;  v[7]=f1.w;
        v[8]=f2.x; v[9]=f2.y; v[10]=f2.z; v[11]=f2.w;

        int tt[2];
        tt[0] = t2.x; tt[1] = t2.y;

        #pragma unroll
        for (int r = 0; r < 2; r++) {
            const int base = r * 6;
            float bv = v[base];
            int   bi = 0;
            #pragma unroll
            for (int c = 1; c < 6; c++) {
                // strict > keeps FIRST max, matching jnp.argmax tie-break
                if (v[base + c] > bv) { bv = v[base + c]; bi = c; }
            }
            const int t = tt[r];
            const int d = t - bi;
            dsum    += (unsigned)(d * d);
            ht_pack += 1ull << (t  * 10);
            hp_pack += 1ull << (bi * 10);
        }
    }

    // Tail row (n odd): block 0, thread 0.
    if (blockIdx.x == 0 && tid == 0 && (n & 1)) {
        const int r = n - 1;
        const float* row = yp + (size_t)r * 6;
        float bv = row[0];
        int   bi = 0;
        #pragma unroll
        for (int c = 1; c < 6; c++) {
            float x = row[c];
            if (x > bv) { bv = x; bi = c; }
        }
        const int t = yt[r];
        const int d = t - bi;
        dsum    += (unsigned)(d * d);
        ht_pack += 1ull << (t  * 10);
        hp_pack += 1ull << (bi * 10);
    }

    // Unpack to 13 u32 and warp shuffle-reduce.
    unsigned int vals[NVALS];
    #pragma unroll
    for (int c = 0; c < NC; c++) {
        vals[c]      = (unsigned int)((ht_pack >> (c * 10)) & 0x3FFu);
        vals[NC + c] = (unsigned int)((hp_pack >> (c * 10)) & 0x3FFu);
    }
    vals[12] = dsum;

    #pragma unroll
    for (int k = 0; k < NVALS; k++) {
        unsigned int s = vals[k];
        #pragma unroll
        for (int o = 16; o; o >>= 1)
            s += __shfl_xor_sync(0xffffffffu, s, o);
        vals[k] = s;
    }

    // Block merge via shared: lane 0 of each warp deposits its 13 sums.
    __shared__ unsigned int s_w[NWARPS][NVALS];
    if (lane == 0) {
        #pragma unroll
        for (int k = 0; k < NVALS; k++) s_w[warp][k] = vals[k];
    }
    __syncthreads();
    if (tid < NVALS) {
        unsigned int s = 0;
        #pragma unroll
        for (int w = 0; w < NWARPS; w++) s += s_w[w][tid];
        g_part[tid][blockIdx.x] = s;
    }
    __threadfence();   // release partials
    __syncthreads();

    // Last-block-done: final reduce + kappa.
    __shared__ unsigned int s_last;
    __shared__ unsigned int s_acc[NVALS];
    if (tid == 0)
        s_last = (atomicAdd(&g_ticket, 1u) == (unsigned)(gridDim.x - 1)) ? 1u : 0u;
    __syncthreads();
    if (!s_last) return;

    __threadfence();   // acquire: all blocks' partials visible

    if (tid < NVALS) s_acc[tid] = 0u;
    __syncthreads();

    // 13 values x 19 slices = 247 active threads.
    {
        const int k     = tid % NVALS;
        const int slice = tid / NVALS;
        if (slice < 19) {
            volatile const unsigned int* row = &g_part[k][0];
            unsigned int s = 0;
            for (int b = slice; b < NBLOCKS; b += 19) s += row[b];
            atomicAdd(&s_acc[k], s);
        }
    }
    __syncthreads();

    if (tid == 0) {
        double ht[NC], hp[NC];
        #pragma unroll
        for (int c = 0; c < NC; c++) {
            ht[c] = (double)s_acc[c];
            hp[c] = (double)s_acc[NC + c];
        }
        const double num = (double)s_acc[12];   // sum W*conf (unnormalized)
        double den = 0.0;
        #pragma unroll
        for (int i = 0; i < NC; i++)
            #pragma unroll
            for (int j = 0; j < NC; j++)
                den += (double)((i - j) * (i - j)) * ht[i] * hp[j];
        const double N = (double)n;
        out[0] = (float)(1.0 - (num * N) / den);
        g_ticket = 0u;   // reset for next graph replay (deterministic)
    }
}

extern "C" void kernel_launch(void* const* d_in, const int* in_sizes, int n_in,
                              void* d_out, int out_size) {
    const float* yp  = (const float*)d_in[0];
    const int*   yt  = (const int*)d_in[1];
    float*       out = (float*)d_out;
    const int n = in_sizes[1];   // number of rows (y_true element count)

    kappa_fused_kernel<<<NBLOCKS, TPB>>>(yp, yt, n, out);
}

// round 14
// speedup vs baseline: 1.3265x; 1.3265x over previous
#include <cuda_runtime.h>

#define NC      6
#define NWARPS  8
#define TPB     256
#define NBLOCKS 592    // 148 SMs * 4 (4 CTAs/SM, 64-reg budget)
#define NVALS   13     // ht[6], hp[6], dsum

// Per-block partials, [val][block]; fully overwritten each launch.
__device__ unsigned int g_part[NVALS][NBLOCKS];
__device__ unsigned int g_ticket;   // last-block-done counter; reset by last block

__device__ __forceinline__ void process2(
    float4 f0, float4 f1, float4 f2, int2 t2,
    unsigned long long& ht_pack, unsigned long long& hp_pack, unsigned int& dsum)
{
    float v[12];
    v[0]=f0.x; v[1]=f0.y; v[2]=f0.z;  v[3]=f0.w;
    v[4]=f1.x; v[5]=f1.y; v[6]=f1.z;  v[7]=f1.w;
    v[8]=f2.x; v[9]=f2.y; v[10]=f2.z; v[11]=f2.w;

    int tt[2];
    tt[0] = t2.x; tt[1] = t2.y;

    #pragma unroll
    for (int r = 0; r < 2; r++) {
        const int base = r * 6;
        float bv = v[base];
        int   bi = 0;
        #pragma unroll
        for (int c = 1; c < 6; c++) {
            // strict > keeps FIRST max, matching jnp.argmax tie-break
            if (v[base + c] > bv) { bv = v[base + c]; bi = c; }
        }
        const int t = tt[r];
        const int d = t - bi;
        dsum    += (unsigned)(d * d);
        ht_pack += 1ull << (t  * 10);
        hp_pack += 1ull << (bi * 10);
    }
}

__global__ void __launch_bounds__(TPB, 4) kappa_fused_kernel(
    const float* __restrict__ yp,
    const int* __restrict__ yt,     // y_true is int32 (JAX x64-demotion)
    int n,
    float* __restrict__ out)
{
    // Per-warp transpose buffer: 96 float4 = one 64-row chunk.
    __shared__ float4 xbuf[NWARPS][96];   // 12 KB

    const int tid  = threadIdx.x;
    const int warp = tid >> 5;
    const int lane = tid & 31;

    // Register accumulators: packed 6x10-bit histograms + squared-diff sum.
    unsigned long long ht_pack = 0ull;
    unsigned long long hp_pack = 0ull;
    unsigned int dsum = 0u;

    const float4* yp4 = (const float4*)yp;
    const int2*   yt2 = (const int2*)yt;

    const int nchunks = n >> 6;                       // 64 rows per warp-chunk
    const int gw = blockIdx.x * NWARPS + warp;        // global warp id
    const int nw = gridDim.x * NWARPS;                // total warps

    int c = gw;
    bool have = (c < nchunks);

    // Warp-coalesced loads: lane-contiguous float4 (4 lines per LDG.128,
    // vs 12 for the thread-strided layout -> ~3x fewer L1TEX wavefronts).
    float4 v0, v1, v2; int2 tn;
    if (have) {
        const float4* p = yp4 + (size_t)c * 96;
        v0 = __ldcg(p + lane);
        v1 = __ldcg(p + 32 + lane);
        v2 = __ldcg(p + 64 + lane);
        tn = __ldcg(yt2 + (size_t)c * 32 + lane);     // rows 2*lane, 2*lane+1
    }

    while (have) {
        const int  cn    = c + nw;
        const bool haven = (cn < nchunks);

        // Stage current chunk into the warp's smem slot (lane-major: conflict-free).
        xbuf[warp][lane]      = v0;
        xbuf[warp][lane + 32] = v1;
        xbuf[warp][lane + 64] = v2;
        const int2 tcur = tn;

        // Prefetch next chunk while this one is consumed (keeps 1792B/warp in flight).
        if (haven) {
            const float4* p = yp4 + (size_t)cn * 96;
            v0 = __ldcg(p + lane);
            v1 = __ldcg(p + 32 + lane);
            v2 = __ldcg(p + 64 + lane);
            tn = __ldcg(yt2 + (size_t)cn * 32 + lane);
        }

        __syncwarp();
        // Read back thread-major: float4 indices 3*lane..3*lane+2 = this
        // thread's 2 rows. Stride-3 float4: each 8-lane phase tiles all 32
        // banks exactly once -> conflict-free.
        float4 f0 = xbuf[warp][3 * lane + 0];
        float4 f1 = xbuf[warp][3 * lane + 1];
        float4 f2 = xbuf[warp][3 * lane + 2];
        __syncwarp();   // all lanes done reading before next iter's STS

        process2(f0, f1, f2, tcur, ht_pack, hp_pack, dsum);

        c = cn; have = haven;
    }

    // Tail rows (n % 64): block 0, scalar per thread.
    if (blockIdx.x == 0) {
        const int tbase = nchunks << 6;
        for (int r = tbase + tid; r < n; r += TPB) {
            const float* row = yp + (size_t)r * 6;
            float bv = row[0];
            int   bi = 0;
            #pragma unroll
            for (int cc = 1; cc < 6; cc++) {
                float x = row[cc];
                if (x > bv) { bv = x; bi = cc; }
            }
            const int t = yt[r];
            const int d = t - bi;
            dsum    += (unsigned)(d * d);
            ht_pack += 1ull << (t  * 10);
            hp_pack += 1ull << (bi * 10);
        }
    }

    // Unpack to 13 u32 and warp shuffle-reduce.
    unsigned int vals[NVALS];
    #pragma unroll
    for (int cc = 0; cc < NC; cc++) {
        vals[cc]      = (unsigned int)((ht_pack >> (cc * 10)) & 0x3FFu);
        vals[NC + cc] = (unsigned int)((hp_pack >> (cc * 10)) & 0x3FFu);
    }
    vals[12] = dsum;

    #pragma unroll
    for (int k = 0; k < NVALS; k++) {
        unsigned int s = vals[k];
        #pragma unroll
        for (int o = 16; o; o >>= 1)
            s += __shfl_xor_sync(0xffffffffu, s, o);
        vals[k] = s;
    }

    // Block merge via shared: lane 0 of each warp deposits its 13 sums.
    __shared__ unsigned int s_w[NWARPS][NVALS];
    if (lane == 0) {
        #pragma unroll
        for (int k = 0; k < NVALS; k++) s_w[warp][k] = vals[k];
    }
    __syncthreads();
    if (tid < NVALS) {
        unsigned int s = 0;
        #pragma unroll
        for (int w = 0; w < NWARPS; w++) s += s_w[w][tid];
        g_part[tid][blockIdx.x] = s;
    }
    __threadfence();   // release partials
    __syncthreads();

    // Last-block-done: final reduce + kappa.
    __shared__ unsigned int s_last;
    __shared__ unsigned int s_acc[NVALS];
    if (tid == 0)
        s_last = (atomicAdd(&g_ticket, 1u) == (unsigned)(gridDim.x - 1)) ? 1u : 0u;
    __syncthreads();
    if (!s_last) return;

    __threadfence();   // acquire: all blocks' partials visible

    if (tid < NVALS) s_acc[tid] = 0u;
    __syncthreads();

    // 13 values x 19 slices = 247 active threads.
    {
        const int k     = tid % NVALS;
        const int slice = tid / NVALS;
        if (slice < 19) {
            volatile const unsigned int* row = &g_part[k][0];
            unsigned int s = 0;
            for (int b = slice; b < NBLOCKS; b += 19) s += row[b];
            atomicAdd(&s_acc[k], s);
        }
    }
    __syncthreads();

    if (tid == 0) {
        double ht[NC], hp[NC];
        #pragma unroll
        for (int cc = 0; cc < NC; cc++) {
            ht[cc] = (double)s_acc[cc];
            hp[cc] = (double)s_acc[NC + cc];
        }
        const double num = (double)s_acc[12];   // sum W*conf (unnormalized)
        double den = 0.0;
        #pragma unroll
        for (int i = 0; i < NC; i++)
            #pragma unroll
            for (int j = 0; j < NC; j++)
                den += (double)((i - j) * (i - j)) * ht[i] * hp[j];
        const double N = (double)n;
        out[0] = (float)(1.0 - (num * N) / den);
        g_ticket = 0u;   // reset for next graph replay (deterministic)
    }
}

extern "C" void kernel_launch(void* const* d_in, const int* in_sizes, int n_in,
                              void* d_out, int out_size) {
    const float* yp  = (const float*)d_in[0];
    const int*   yt  = (const int*)d_in[1];
    float*       out = (float*)d_out;
    const int n = in_sizes[1];   // number of rows (y_true element count)

    kappa_fused_kernel<<<NBLOCKS, TPB>>>(yp, yt, n, out);
}